// round 12
// baseline (speedup 1.0000x reference)
#include <cuda_runtime.h>
#include <cuda_bf16.h>
#include <cstdint>

// Problem constants
#define BB 4
#define TT 2048
#define CC 768
#define HH 12
#define DD 64
#define NQ (BB * HH * TT * DD)

// Pre-split bf16 hi/lo tensors
__device__ __nv_bfloat16 g_qh[NQ], g_ql[NQ];
__device__ __nv_bfloat16 g_kh[NQ], g_kl[NQ];
__device__ __nv_bfloat16 g_vh[NQ], g_vl[NQ];
__device__ __nv_bfloat16 g_oh[BB * TT * CC], g_ol[BB * TT * CC];
__device__ __nv_bfloat16 g_xh[BB * TT * CC], g_xl[BB * TT * CC];
__device__ __nv_bfloat16 g_wqh[3 * CC * CC], g_wql[3 * CC * CC];
__device__ __nv_bfloat16 g_wph[CC * CC], g_wpl[CC * CC];

static __device__ __forceinline__ uint32_t smem_u32(const void* p) {
    uint32_t a;
    asm("{ .reg .u64 t; cvta.to.shared.u64 t, %1; cvt.u32.u64 %0, t; }"
        : "=r"(a) : "l"(p));
    return a;
}

static __device__ __forceinline__ void ldm4(uint32_t* r, uint32_t addr) {
    asm volatile("ldmatrix.sync.aligned.m8n8.x4.shared.b16 {%0,%1,%2,%3}, [%4];"
                 : "=r"(r[0]), "=r"(r[1]), "=r"(r[2]), "=r"(r[3]) : "r"(addr));
}
static __device__ __forceinline__ void ldm4t(uint32_t* r, uint32_t addr) {
    asm volatile("ldmatrix.sync.aligned.m8n8.x4.trans.shared.b16 {%0,%1,%2,%3}, [%4];"
                 : "=r"(r[0]), "=r"(r[1]), "=r"(r[2]), "=r"(r[3]) : "r"(addr));
}

static __device__ __forceinline__ void mma16816(float* d, const uint32_t* a,
                                                const uint32_t* b) {
    asm volatile(
        "mma.sync.aligned.m16n8k16.row.col.f32.bf16.bf16.f32 "
        "{%0,%1,%2,%3}, {%4,%5,%6,%7}, {%8,%9}, {%0,%1,%2,%3};"
        : "+f"(d[0]), "+f"(d[1]), "+f"(d[2]), "+f"(d[3])
        : "r"(a[0]), "r"(a[1]), "r"(a[2]), "r"(a[3]), "r"(b[0]), "r"(b[1]));
}

static __device__ __forceinline__ void split2(float f0, float f1,
                                              uint32_t& hi, uint32_t& lo) {
    __nv_bfloat16 h0 = __float2bfloat16(f0);
    __nv_bfloat16 h1 = __float2bfloat16(f1);
    __nv_bfloat16 l0 = __float2bfloat16(f0 - __bfloat162float(h0));
    __nv_bfloat16 l1 = __float2bfloat16(f1 - __bfloat162float(h1));
    __nv_bfloat162 hh = __halves2bfloat162(h0, h1);
    __nv_bfloat162 ll = __halves2bfloat162(l0, l1);
    hi = *reinterpret_cast<uint32_t*>(&hh);
    lo = *reinterpret_cast<uint32_t*>(&ll);
}

// FMA-pipe exp2 (no MUFU). Valid for x <= 0; clamps at -126.
static __device__ __forceinline__ float exp2f_fast(float x) {
    x = fmaxf(x, -126.0f);
    float z = x + 12582912.0f;
    int i = __float_as_int(z) - 0x4B400000;
    float f = x - (z - 12582912.0f);
    float p = 0.00133336f;
    p = fmaf(p, f, 0.00961813f);
    p = fmaf(p, f, 0.05550411f);
    p = fmaf(p, f, 0.24022651f);
    p = fmaf(p, f, 0.69314718f);
    p = fmaf(p, f, 1.0f);
    return p * __int_as_float((i + 127) << 23);
}
#define L2E 1.4426950408889634f

#define STS4(addr, a, b, c, d) \
    asm volatile("st.shared.v4.b32 [%0], {%1,%2,%3,%4};" :: \
                 "r"(addr), "r"(a), "r"(b), "r"(c), "r"(d) : "memory")
#define CP16(dst, src) \
    asm volatile("cp.async.ca.shared.global [%0], [%1], 16;" :: \
                 "r"(dst), "l"(src) : "memory")
#define CP_COMMIT() asm volatile("cp.async.commit_group;" ::: "memory")
#define CP_WAIT1()  asm volatile("cp.async.wait_group 1;" ::: "memory")
#define CP_WAIT0()  asm volatile("cp.async.wait_group 0;" ::: "memory")

// ===========================================================================
// Split kernel: fp32 -> bf16 hi/lo (vectorized, grid-stride)
// ===========================================================================
__global__ void split_kernel(const float* __restrict__ src,
                             __nv_bfloat16* __restrict__ h,
                             __nv_bfloat16* __restrict__ l, int n4)
{
    for (int i = blockIdx.x * blockDim.x + threadIdx.x; i < n4;
         i += gridDim.x * blockDim.x) {
        float4 v = ((const float4*)src)[i];
        uint32_t h01, l01, h23, l23;
        split2(v.x, v.y, h01, l01);
        split2(v.z, v.w, h23, l23);
        ((uint2*)h)[i] = make_uint2(h01, h23);
        ((uint2*)l)[i] = make_uint2(l01, l23);
    }
}

// ===========================================================================
// GEMM v6: split-bf16 HMMA, cp.async 2-stage, K-chunk 32 (192 MMA/warp
// between barriers -- the ratio the attention kernel proves efficient).
// CTA 256(M) x 128(N), 8 warps = 4M x 2N, warp tile 64x64.
// Stage (80B row stride, conflict-free for consecutive 8 rows):
//   Ah[256][80] @0 | Al @20480 | Bh[128][80] @40960 | Bl @51200 = 61440B
// 2 stages = 122880B dynamic smem (opt-in). 1 CTA/SM x 8 warps.
// EPI 0: RoPE scatter -> g_{q,k,v}{h,l}. EPI 1: fp32 store to outp.
// ===========================================================================
#define GST2 80
#define STAGE_B 61440
#define GEMM_SMEM (2 * STAGE_B)
#define NCHUNK 24

template <int EPI>
__global__ __launch_bounds__(256, 1) void gemm_mma_kernel(
    const float* __restrict__ rsin, const float* __restrict__ rcos,
    float* __restrict__ outp)
{
    extern __shared__ __align__(16) char smem[];
    const uint32_t sb = smem_u32(smem);

    const int tid = threadIdx.x;
    const int lane = tid & 31, warp = tid >> 5;
    const int warpM = warp & 3, warpN = warp >> 2;   // 4 x 2
    const int mBase = blockIdx.y * 256, nBase = blockIdx.x * 128;

    const __nv_bfloat16* Ah = (EPI == 0) ? g_xh : g_oh;
    const __nv_bfloat16* Al = (EPI == 0) ? g_xl : g_ol;
    const __nv_bfloat16* Bh = (EPI == 0) ? g_wqh : g_wph;
    const __nv_bfloat16* Bl = (EPI == 0) ? g_wql : g_wpl;

    // loader: thread t owns A row t (hi+lo); B row t&127, buffer t>>7
    const int bRow = tid & 127, bSel = tid >> 7;
    const __nv_bfloat16* sAh = Ah + (size_t)(mBase + tid) * 768;
    const __nv_bfloat16* sAl = Al + (size_t)(mBase + tid) * 768;
    const __nv_bfloat16* sB  = (bSel ? Bl : Bh) + (size_t)(nBase + bRow) * 768;
    const uint32_t dAh = sb + (uint32_t)tid * GST2;
    const uint32_t dAl = dAh + 20480;
    const uint32_t dB  = sb + 40960 + (uint32_t)bSel * 10240 + (uint32_t)bRow * GST2;

    const uint32_t aoff = sb +
        (uint32_t)(warpM * 64 + (lane & 7) + ((lane >> 3) & 1) * 8) * GST2 +
        ((lane >> 4) & 1) * 16;
    const uint32_t boff = sb + 40960 +
        (uint32_t)(warpN * 64 + (lane & 7) + ((lane >> 4) & 1) * 8) * GST2 +
        ((lane >> 3) & 1) * 16;

    float acc[4][8][4];
#pragma unroll
    for (int mt = 0; mt < 4; mt++)
#pragma unroll
        for (int nt = 0; nt < 8; nt++)
#pragma unroll
            for (int r = 0; r < 4; r++) acc[mt][nt][r] = 0.0f;

    // prologue: stage 0 (A: 8x16B hi+lo, B: 4x16B)
#pragma unroll
    for (int g = 0; g < 4; g++) {
        CP16(dAh + g * 16, sAh + g * 8);
        CP16(dAl + g * 16, sAl + g * 8);
        CP16(dB + g * 16, sB + g * 8);
    }
    CP_COMMIT();

    for (int c = 0; c < NCHUNK; c++) {
        const uint32_t stOff = (uint32_t)(c & 1) * STAGE_B;
        if (c + 1 < NCHUNK) {
            const uint32_t ns = (uint32_t)((c + 1) & 1) * STAGE_B;
            const int ko = (c + 1) * 32;
#pragma unroll
            for (int g = 0; g < 4; g++) {
                CP16(dAh + ns + g * 16, sAh + ko + g * 8);
                CP16(dAl + ns + g * 16, sAl + ko + g * 8);
                CP16(dB + ns + g * 16, sB + ko + g * 8);
            }
            CP_COMMIT();
            CP_WAIT1();          // stage c arrived
        } else {
            CP_WAIT0();
        }
        __syncthreads();

#pragma unroll
        for (int kh = 0; kh < 2; kh++) {
            const uint32_t khb = kh * 32;
            uint32_t bh[4][4], bl[4][4];
#pragma unroll
            for (int p = 0; p < 4; p++) {
                ldm4(bh[p], boff + stOff + p * (16 * GST2) + khb);
                ldm4(bl[p], boff + stOff + 10240 + p * (16 * GST2) + khb);
            }
#pragma unroll
            for (int mt = 0; mt < 4; mt++) {
                uint32_t ah[4], al[4];
                ldm4(ah, aoff + stOff + mt * (16 * GST2) + khb);
                ldm4(al, aoff + stOff + 20480 + mt * (16 * GST2) + khb);
#pragma unroll
                for (int nt = 0; nt < 8; nt++) {
                    const uint32_t* bhf = &bh[nt >> 1][(nt & 1) * 2];
                    const uint32_t* blf = &bl[nt >> 1][(nt & 1) * 2];
                    mma16816(acc[mt][nt], ah, bhf);
                    mma16816(acc[mt][nt], ah, blf);
                    mma16816(acc[mt][nt], al, bhf);
                }
            }
        }
        __syncthreads();   // protect stage c before refill at c+2
    }

    const int gRow = lane >> 2;
    const int gCol = (lane & 3) * 2;
#pragma unroll
    for (int mt = 0; mt < 4; mt++) {
#pragma unroll
        for (int half = 0; half < 2; half++) {
            const int row_g = mBase + warpM * 64 + mt * 16 + gRow + half * 8;
#pragma unroll
            for (int nt = 0; nt < 8; nt++) {
                const float v1 = acc[mt][nt][half * 2];
                const float v2 = acc[mt][nt][half * 2 + 1];
                const int col_g = nBase + warpN * 64 + nt * 8 + gCol;
                if (EPI == 0) {
                    const int b = row_g >> 11, t = row_g & 2047;
                    const int s_idx = nBase / 768;
                    const int rem = col_g - s_idx * 768;
                    const int h = rem >> 6, d = rem & 63;
                    const size_t off = ((size_t)(b * HH + h) * TT + t) * DD + d;
                    uint32_t hi, lo;
                    if (s_idx < 2) {
                        const float sc = (s_idx == 0) ? 0.125f : 1.0f;
                        const float sn = rsin[t * 32 + (d >> 1)];
                        const float cs = rcos[t * 32 + (d >> 1)];
                        split2((v1 * cs - v2 * sn) * sc,
                               (v1 * sn + v2 * cs) * sc, hi, lo);
                        __nv_bfloat16* dh = (s_idx == 0) ? g_qh : g_kh;
                        __nv_bfloat16* dl = (s_idx == 0) ? g_ql : g_kl;
                        *(uint32_t*)(dh + off) = hi;
                        *(uint32_t*)(dl + off) = lo;
                    } else {
                        split2(v1, v2, hi, lo);
                        *(uint32_t*)(g_vh + off) = hi;
                        *(uint32_t*)(g_vl + off) = lo;
                    }
                } else {
                    *(float2*)(outp + (size_t)row_g * 768 + col_g) =
                        make_float2(v1, v2);
                }
            }
        }
    }
}

// ===========================================================================
// Flash attention, split-bf16 HMMA, pre-split operands (unchanged, round-8).
// ===========================================================================
#define KST 144

__global__ __launch_bounds__(256) void attn_mma_kernel()
{
    __shared__ __align__(16) char smem[36864];
    const uint32_t sb = smem_u32(smem);
    const uint32_t sKhi = sb, sKlo = sb + 9216;
    const uint32_t sVhi = sb + 18432, sVlo = sb + 27648;

    const int tid = threadIdx.x, lane = tid & 31, warp = tid >> 5;
    const int qi = gridDim.x - 1 - blockIdx.x;
    const int bh = blockIdx.y;
    const size_t bhOff = (size_t)bh * TT * DD;
    const int qBase = qi * 128;

    {
        const int row = tid >> 1, half = tid & 1;
        const uint4* ph = (const uint4*)(g_qh + bhOff + (size_t)(qBase + row) * 64 + half * 32);
        const uint4* pl = (const uint4*)(g_ql + bhOff + (size_t)(qBase + row) * 64 + half * 32);
        const uint32_t dh = sb + (uint32_t)row * KST + half * 64;
#pragma unroll
        for (int g = 0; g < 4; g++) {
            uint4 h = ph[g], l = pl[g];
            STS4(dh + g * 16, h.x, h.y, h.z, h.w);
            STS4(dh + 18432 + g * 16, l.x, l.y, l.z, l.w);
        }
    }
    __syncthreads();

    uint32_t qh[4][4], ql[4][4];
    {
        const uint32_t aoff = sb +
            (uint32_t)(warp * 16 + (lane & 7) + ((lane >> 3) & 1) * 8) * KST +
            ((lane >> 4) & 1) * 16;
#pragma unroll
        for (int kh = 0; kh < 4; kh++) {
            ldm4(qh[kh], aoff + kh * 32);
            ldm4(ql[kh], aoff + 18432 + kh * 32);
        }
    }
    __syncthreads();

    float o[8][4];
#pragma unroll
    for (int dn = 0; dn < 8; dn++)
#pragma unroll
        for (int r = 0; r < 4; r++) o[dn][r] = 0.0f;
    float mrow[2] = {-1e30f, -1e30f};
    float lrow[2] = {0.0f, 0.0f};

    const uint32_t boff =
        (uint32_t)((lane & 7) + ((lane >> 4) & 1) * 8) * KST +
        ((lane >> 3) & 1) * 16;
    const uint32_t voff =
        (uint32_t)((lane & 7) + ((lane >> 3) & 1) * 8) * KST +
        ((lane >> 4) & 1) * 16;
    const int jtEnd = 2 * qi + 1;

    for (int jt = 0; jt <= jtEnd; jt++) {
        {
            const size_t src0 = bhOff + (size_t)jt * 64 * 64;
#pragma unroll
            for (int g = 0; g < 2; g++) {
                const int id = tid + g * 256;
                const int row = id >> 3, part = id & 7;
                const size_t s = src0 + (size_t)row * 64 + part * 8;
                const uint32_t d = (uint32_t)row * KST + part * 16;
                uint4 v;
                v = *(const uint4*)(g_kh + s); STS4(sKhi + d, v.x, v.y, v.z, v.w);
                v = *(const uint4*)(g_kl + s); STS4(sKlo + d, v.x, v.y, v.z, v.w);
                v = *(const uint4*)(g_vh + s); STS4(sVhi + d, v.x, v.y, v.z, v.w);
                v = *(const uint4*)(g_vl + s); STS4(sVlo + d, v.x, v.y, v.z, v.w);
            }
        }
        __syncthreads();

        float s[8][4];
#pragma unroll
        for (int nt = 0; nt < 8; nt++)
#pragma unroll
            for (int r = 0; r < 4; r++) s[nt][r] = 0.0f;
#pragma unroll
        for (int kh = 0; kh < 4; kh++) {
#pragma unroll
            for (int p = 0; p < 4; p++) {
                uint32_t kbh[4], kbl[4];
                ldm4(kbh, sKhi + boff + p * (16 * KST) + kh * 32);
                ldm4(kbl, sKlo + boff + p * (16 * KST) + kh * 32);
#pragma unroll
                for (int sub = 0; sub < 2; sub++) {
                    float* d = s[2 * p + sub];
                    mma16816(d, qh[kh], &kbh[sub * 2]);
                    mma16816(d, qh[kh], &kbl[sub * 2]);
                    mma16816(d, ql[kh], &kbh[sub * 2]);
                }
            }
        }

        if (jt >= 2 * qi) {
            const int row0 = qBase + warp * 16 + (lane >> 2);
            const int colb = jt * 64 + 2 * (lane & 3);
#pragma unroll
            for (int nt = 0; nt < 8; nt++) {
                const int c = colb + nt * 8;
#pragma unroll
                for (int r = 0; r < 4; r++) {
                    const int row = row0 + ((r >> 1) << 3);
                    const int col = c + (r & 1);
                    if (col > row) s[nt][r] = -1e30f;
                }
            }
        }

        float mx0 = -1e30f, mx1 = -1e30f;
#pragma unroll
        for (int nt = 0; nt < 8; nt++) {
            mx0 = fmaxf(mx0, fmaxf(s[nt][0], s[nt][1]));
            mx1 = fmaxf(mx1, fmaxf(s[nt][2], s[nt][3]));
        }
        mx0 = fmaxf(mx0, __shfl_xor_sync(0xffffffffu, mx0, 1));
        mx0 = fmaxf(mx0, __shfl_xor_sync(0xffffffffu, mx0, 2));
        mx1 = fmaxf(mx1, __shfl_xor_sync(0xffffffffu, mx1, 1));
        mx1 = fmaxf(mx1, __shfl_xor_sync(0xffffffffu, mx1, 2));
        const float mn0 = fmaxf(mrow[0], mx0);
        const float mn1 = fmaxf(mrow[1], mx1);
        const float a0 = exp2f_fast((mrow[0] - mn0) * L2E);
        const float a1 = exp2f_fast((mrow[1] - mn1) * L2E);
        mrow[0] = mn0; mrow[1] = mn1;
        float rs0 = 0.0f, rs1 = 0.0f;
#pragma unroll
        for (int nt = 0; nt < 8; nt++) {
            s[nt][0] = exp2f_fast((s[nt][0] - mn0) * L2E);
            s[nt][1] = exp2f_fast((s[nt][1] - mn0) * L2E);
            s[nt][2] = exp2f_fast((s[nt][2] - mn1) * L2E);
            s[nt][3] = exp2f_fast((s[nt][3] - mn1) * L2E);
            rs0 += s[nt][0] + s[nt][1];
            rs1 += s[nt][2] + s[nt][3];
        }
        rs0 += __shfl_xor_sync(0xffffffffu, rs0, 1);
        rs0 += __shfl_xor_sync(0xffffffffu, rs0, 2);
        rs1 += __shfl_xor_sync(0xffffffffu, rs1, 1);
        rs1 += __shfl_xor_sync(0xffffffffu, rs1, 2);
        lrow[0] = lrow[0] * a0 + rs0;
        lrow[1] = lrow[1] * a1 + rs1;
#pragma unroll
        for (int dn = 0; dn < 8; dn++) {
            o[dn][0] *= a0; o[dn][1] *= a0;
            o[dn][2] *= a1; o[dn][3] *= a1;
        }

#pragma unroll
        for (int kh = 0; kh < 4; kh++) {
            uint32_t ph[4], pl[4];
#pragma unroll
            for (int idx = 0; idx < 4; idx++) {
                const int nt = 2 * kh + (idx >> 1);
                const int rb = (idx & 1) * 2;
                split2(s[nt][rb], s[nt][rb + 1], ph[idx], pl[idx]);
            }
#pragma unroll
            for (int p = 0; p < 4; p++) {
                uint32_t vbh[4], vbl[4];
                ldm4t(vbh, sVhi + voff + kh * (16 * KST) + p * 32);
                ldm4t(vbl, sVlo + voff + kh * (16 * KST) + p * 32);
#pragma unroll
                for (int sub = 0; sub < 2; sub++) {
                    float* d = o[2 * p + sub];
                    mma16816(d, ph, &vbh[sub * 2]);
                    mma16816(d, ph, &vbl[sub * 2]);
                    mma16816(d, pl, &vbh[sub * 2]);
                }
            }
        }
        __syncthreads();
    }

    const int b = bh / HH, h = bh % HH;
    const float inv0 = 1.0f / lrow[0];
    const float inv1 = 1.0f / lrow[1];
    const int row0 = qBase + warp * 16 + (lane >> 2);
    const int colb = h * 64 + 2 * (lane & 3);
#pragma unroll
    for (int dn = 0; dn < 8; dn++) {
        const int col = colb + dn * 8;
        uint32_t hi, lo;
        split2(o[dn][0] * inv0, o[dn][1] * inv0, hi, lo);
        *(uint32_t*)(g_oh + (size_t)(b * TT + row0) * CC + col) = hi;
        *(uint32_t*)(g_ol + (size_t)(b * TT + row0) * CC + col) = lo;
        split2(o[dn][2] * inv1, o[dn][3] * inv1, hi, lo);
        *(uint32_t*)(g_oh + (size_t)(b * TT + row0 + 8) * CC + col) = hi;
        *(uint32_t*)(g_ol + (size_t)(b * TT + row0 + 8) * CC + col) = lo;
    }
}

// ---------------------------------------------------------------------------
extern "C" void kernel_launch(void* const* d_in, const int* in_sizes, int n_in,
                              void* d_out, int out_size)
{
    const float* x      = (const float*)d_in[0];
    const float* w_qkv  = (const float*)d_in[1];
    const float* w_proj = (const float*)d_in[2];
    const float* rsin   = (const float*)d_in[3];
    const float* rcos   = (const float*)d_in[4];
    float* out = (float*)d_out;

    __nv_bfloat16 *xh, *xl, *wqh, *wql, *wph, *wpl;
    cudaGetSymbolAddress((void**)&xh,  g_xh);
    cudaGetSymbolAddress((void**)&xl,  g_xl);
    cudaGetSymbolAddress((void**)&wqh, g_wqh);
    cudaGetSymbolAddress((void**)&wql, g_wql);
    cudaGetSymbolAddress((void**)&wph, g_wph);
    cudaGetSymbolAddress((void**)&wpl, g_wpl);

    cudaFuncSetAttribute(gemm_mma_kernel<0>,
                         cudaFuncAttributeMaxDynamicSharedMemorySize, GEMM_SMEM);
    cudaFuncSetAttribute(gemm_mma_kernel<1>,
                         cudaFuncAttributeMaxDynamicSharedMemorySize, GEMM_SMEM);

    split_kernel<<<1024, 256>>>(x, xh, xl, (BB * TT * CC) / 4);
    split_kernel<<<512, 256>>>(w_qkv, wqh, wql, (3 * CC * CC) / 4);
    split_kernel<<<256, 256>>>(w_proj, wph, wpl, (CC * CC) / 4);

    // QKV: M=8192 (32 x 256), N=2304 (18 x 128)
    gemm_mma_kernel<0><<<dim3(18, 32), 256, GEMM_SMEM>>>(rsin, rcos, nullptr);
    // Attention: 16 q-tiles of 128 x 48 (b,h)
    attn_mma_kernel<<<dim3(16, 48), 256>>>();
    // Proj: M=8192, N=768 (6 x 128)
    gemm_mma_kernel<1><<<dim3(6, 32), 256, GEMM_SMEM>>>(rsin, rcos, out);
}

// round 14
// speedup vs baseline: 1.3012x; 1.3012x over previous
#include <cuda_runtime.h>
#include <cuda_bf16.h>
#include <cuda_fp16.h>
#include <cstdint>

// Problem constants
#define BB 4
#define TT 2048
#define CC 768
#define HH 12
#define DD 64
#define NQ (BB * HH * TT * DD)

// Pre-split bf16 hi/lo tensors; V is single fp16
__device__ __nv_bfloat16 g_qh[NQ], g_ql[NQ];
__device__ __nv_bfloat16 g_kh[NQ], g_kl[NQ];
__device__ __half        g_vf[NQ];
__device__ __nv_bfloat16 g_oh[BB * TT * CC], g_ol[BB * TT * CC];
__device__ __nv_bfloat16 g_xh[BB * TT * CC], g_xl[BB * TT * CC];
__device__ __nv_bfloat16 g_wqh[3 * CC * CC], g_wql[3 * CC * CC];
__device__ __nv_bfloat16 g_wph[CC * CC], g_wpl[CC * CC];

static __device__ __forceinline__ uint32_t smem_u32(const void* p) {
    uint32_t a;
    asm("{ .reg .u64 t; cvta.to.shared.u64 t, %1; cvt.u32.u64 %0, t; }"
        : "=r"(a) : "l"(p));
    return a;
}

static __device__ __forceinline__ void ldm4(uint32_t* r, uint32_t addr) {
    asm volatile("ldmatrix.sync.aligned.m8n8.x4.shared.b16 {%0,%1,%2,%3}, [%4];"
                 : "=r"(r[0]), "=r"(r[1]), "=r"(r[2]), "=r"(r[3]) : "r"(addr));
}
static __device__ __forceinline__ void ldm4t(uint32_t* r, uint32_t addr) {
    asm volatile("ldmatrix.sync.aligned.m8n8.x4.trans.shared.b16 {%0,%1,%2,%3}, [%4];"
                 : "=r"(r[0]), "=r"(r[1]), "=r"(r[2]), "=r"(r[3]) : "r"(addr));
}

static __device__ __forceinline__ void mma16816(float* d, const uint32_t* a,
                                                const uint32_t* b) {
    asm volatile(
        "mma.sync.aligned.m16n8k16.row.col.f32.bf16.bf16.f32 "
        "{%0,%1,%2,%3}, {%4,%5,%6,%7}, {%8,%9}, {%0,%1,%2,%3};"
        : "+f"(d[0]), "+f"(d[1]), "+f"(d[2]), "+f"(d[3])
        : "r"(a[0]), "r"(a[1]), "r"(a[2]), "r"(a[3]), "r"(b[0]), "r"(b[1]));
}
static __device__ __forceinline__ void mma16816h(float* d, const uint32_t* a,
                                                 const uint32_t* b) {
    asm volatile(
        "mma.sync.aligned.m16n8k16.row.col.f32.f16.f16.f32 "
        "{%0,%1,%2,%3}, {%4,%5,%6,%7}, {%8,%9}, {%0,%1,%2,%3};"
        : "+f"(d[0]), "+f"(d[1]), "+f"(d[2]), "+f"(d[3])
        : "r"(a[0]), "r"(a[1]), "r"(a[2]), "r"(a[3]), "r"(b[0]), "r"(b[1]));
}

static __device__ __forceinline__ void split2(float f0, float f1,
                                              uint32_t& hi, uint32_t& lo) {
    __nv_bfloat16 h0 = __float2bfloat16(f0);
    __nv_bfloat16 h1 = __float2bfloat16(f1);
    __nv_bfloat16 l0 = __float2bfloat16(f0 - __bfloat162float(h0));
    __nv_bfloat16 l1 = __float2bfloat16(f1 - __bfloat162float(h1));
    __nv_bfloat162 hh = __halves2bfloat162(h0, h1);
    __nv_bfloat162 ll = __halves2bfloat162(l0, l1);
    hi = *reinterpret_cast<uint32_t*>(&hh);
    lo = *reinterpret_cast<uint32_t*>(&ll);
}
static __device__ __forceinline__ uint32_t packh2(float f0, float f1) {
    __half2 h = __floats2half2_rn(f0, f1);
    return *reinterpret_cast<uint32_t*>(&h);
}

// FMA-pipe exp2 (no MUFU). Valid for x <= 0; clamps at -126.
static __device__ __forceinline__ float exp2f_fast(float x) {
    x = fmaxf(x, -126.0f);
    float z = x + 12582912.0f;
    int i = __float_as_int(z) - 0x4B400000;
    float f = x - (z - 12582912.0f);
    float p = 0.00133336f;
    p = fmaf(p, f, 0.00961813f);
    p = fmaf(p, f, 0.05550411f);
    p = fmaf(p, f, 0.24022651f);
    p = fmaf(p, f, 0.69314718f);
    p = fmaf(p, f, 1.0f);
    return p * __int_as_float((i + 127) << 23);
}
#define L2E 1.4426950408889634f

#define STS4(addr, a, b, c, d) \
    asm volatile("st.shared.v4.b32 [%0], {%1,%2,%3,%4};" :: \
                 "r"(addr), "r"(a), "r"(b), "r"(c), "r"(d) : "memory")
#define CP16(dst, src) \
    asm volatile("cp.async.ca.shared.global [%0], [%1], 16;" :: \
                 "r"(dst), "l"(src) : "memory")
#define CP_COMMIT() asm volatile("cp.async.commit_group;" ::: "memory")
#define CP_WAIT1()  asm volatile("cp.async.wait_group 1;" ::: "memory")
#define CP_WAIT0()  asm volatile("cp.async.wait_group 0;" ::: "memory")

// ===========================================================================
// Split kernel: fp32 -> bf16 hi/lo (vectorized, grid-stride)
// ===========================================================================
__global__ void split_kernel(const float* __restrict__ src,
                             __nv_bfloat16* __restrict__ h,
                             __nv_bfloat16* __restrict__ l, int n4)
{
    for (int i = blockIdx.x * blockDim.x + threadIdx.x; i < n4;
         i += gridDim.x * blockDim.x) {
        float4 v = ((const float4*)src)[i];
        uint32_t h01, l01, h23, l23;
        split2(v.x, v.y, h01, l01);
        split2(v.z, v.w, h23, l23);
        ((uint2*)h)[i] = make_uint2(h01, h23);
        ((uint2*)l)[i] = make_uint2(l01, l23);
    }
}

// ===========================================================================
// GEMM v4 (round-11 config, best measured): split-bf16 HMMA, cp.async
// 2-stage ping-pong, warp tile 64x64, CTA 128x128, 4 warps, 2 CTAs/SM.
// EPI 0: RoPE scatter -> g_qh/ql, g_kh/kl, V -> g_vf (fp16 single).
// EPI 1: fp32 store to outp.
// ===========================================================================
#define GST 48
#define STAGE_B 24576
#define NCHUNK 48

template <int EPI>
__global__ __launch_bounds__(128, 2) void gemm_mma_kernel(
    const float* __restrict__ rsin, const float* __restrict__ rcos,
    float* __restrict__ outp)
{
    __shared__ __align__(16) char smem[2 * STAGE_B];
    const uint32_t sb = smem_u32(smem);

    const int tid = threadIdx.x;
    const int lane = tid & 31, warp = tid >> 5;
    const int warpM = warp & 1, warpN = warp >> 1;   // 2 x 2
    const int mBase = blockIdx.y * 128, nBase = blockIdx.x * 128;

    const __nv_bfloat16* Ah = (EPI == 0) ? g_xh : g_oh;
    const __nv_bfloat16* Al = (EPI == 0) ? g_xl : g_ol;
    const __nv_bfloat16* Bh = (EPI == 0) ? g_wqh : g_wph;
    const __nv_bfloat16* Bl = (EPI == 0) ? g_wql : g_wpl;

    const __nv_bfloat16* sAh = Ah + (size_t)(mBase + tid) * 768;
    const __nv_bfloat16* sAl = Al + (size_t)(mBase + tid) * 768;
    const __nv_bfloat16* sBh = Bh + (size_t)(nBase + tid) * 768;
    const __nv_bfloat16* sBl = Bl + (size_t)(nBase + tid) * 768;
    const uint32_t dAh = sb + (uint32_t)tid * GST;
    const uint32_t dAl = dAh + 6144;
    const uint32_t dBh = dAh + 12288;
    const uint32_t dBl = dAh + 18432;

    const uint32_t aoff = sb +
        (uint32_t)(warpM * 64 + (lane & 7) + ((lane >> 3) & 1) * 8) * GST +
        ((lane >> 4) & 1) * 16;
    const uint32_t boff = sb + 12288 +
        (uint32_t)(warpN * 64 + (lane & 7) + ((lane >> 4) & 1) * 8) * GST +
        ((lane >> 3) & 1) * 16;

    float acc[4][8][4];
#pragma unroll
    for (int mt = 0; mt < 4; mt++)
#pragma unroll
        for (int nt = 0; nt < 8; nt++)
#pragma unroll
            for (int r = 0; r < 4; r++) acc[mt][nt][r] = 0.0f;

    CP16(dAh, sAh); CP16(dAh + 16, sAh + 8);
    CP16(dAl, sAl); CP16(dAl + 16, sAl + 8);
    CP16(dBh, sBh); CP16(dBh + 16, sBh + 8);
    CP16(dBl, sBl); CP16(dBl + 16, sBl + 8);
    CP_COMMIT();

    for (int c = 0; c < NCHUNK; c++) {
        const uint32_t stOff = (uint32_t)(c & 1) * STAGE_B;
        if (c + 1 < NCHUNK) {
            const uint32_t ns = (uint32_t)((c + 1) & 1) * STAGE_B;
            const int ko = (c + 1) * 16;
            CP16(dAh + ns, sAh + ko); CP16(dAh + ns + 16, sAh + ko + 8);
            CP16(dAl + ns, sAl + ko); CP16(dAl + ns + 16, sAl + ko + 8);
            CP16(dBh + ns, sBh + ko); CP16(dBh + ns + 16, sBh + ko + 8);
            CP16(dBl + ns, sBl + ko); CP16(dBl + ns + 16, sBl + ko + 8);
            CP_COMMIT();
            CP_WAIT1();
        } else {
            CP_WAIT0();
        }
        __syncthreads();

        uint32_t bh[4][4], bl[4][4];
#pragma unroll
        for (int p = 0; p < 4; p++) {
            ldm4(bh[p], boff + stOff + p * (16 * GST));
            ldm4(bl[p], boff + stOff + 6144 + p * (16 * GST));
        }
#pragma unroll
        for (int mt = 0; mt < 4; mt++) {
            uint32_t ah[4], al[4];
            ldm4(ah, aoff + stOff + mt * (16 * GST));
            ldm4(al, aoff + stOff + 6144 + mt * (16 * GST));
#pragma unroll
            for (int nt = 0; nt < 8; nt++) {
                const uint32_t* bhf = &bh[nt >> 1][(nt & 1) * 2];
                const uint32_t* blf = &bl[nt >> 1][(nt & 1) * 2];
                mma16816(acc[mt][nt], ah, bhf);
                mma16816(acc[mt][nt], ah, blf);
                mma16816(acc[mt][nt], al, bhf);
            }
        }
        __syncthreads();
    }

    const int gRow = lane >> 2;
    const int gCol = (lane & 3) * 2;
#pragma unroll
    for (int mt = 0; mt < 4; mt++) {
#pragma unroll
        for (int half = 0; half < 2; half++) {
            const int row_g = mBase + warpM * 64 + mt * 16 + gRow + half * 8;
#pragma unroll
            for (int nt = 0; nt < 8; nt++) {
                const float v1 = acc[mt][nt][half * 2];
                const float v2 = acc[mt][nt][half * 2 + 1];
                const int col_g = nBase + warpN * 64 + nt * 8 + gCol;
                if (EPI == 0) {
                    const int b = row_g >> 11, t = row_g & 2047;
                    const int s_idx = nBase / 768;
                    const int rem = col_g - s_idx * 768;
                    const int h = rem >> 6, d = rem & 63;
                    const size_t off = ((size_t)(b * HH + h) * TT + t) * DD + d;
                    if (s_idx < 2) {
                        const float sc = (s_idx == 0) ? 0.125f : 1.0f;
                        const float sn = rsin[t * 32 + (d >> 1)];
                        const float cs = rcos[t * 32 + (d >> 1)];
                        uint32_t hi, lo;
                        split2((v1 * cs - v2 * sn) * sc,
                               (v1 * sn + v2 * cs) * sc, hi, lo);
                        __nv_bfloat16* dh = (s_idx == 0) ? g_qh : g_kh;
                        __nv_bfloat16* dl = (s_idx == 0) ? g_ql : g_kl;
                        *(uint32_t*)(dh + off) = hi;
                        *(uint32_t*)(dl + off) = lo;
                    } else {
                        *(uint32_t*)(g_vf + off) = packh2(v1, v2);
                    }
                } else {
                    *(float2*)(outp + (size_t)row_g * 768 + col_g) =
                        make_float2(v1, v2);
                }
            }
        }
    }
}

// ===========================================================================
// Flash attention: S = split-bf16 3-MMA (unchanged); O = P(fp16) x V(fp16)
// single MMA. Smem: Khi[64][144] | Klo | Vf  (Vf fp16, 64x128B rows).
// ===========================================================================
#define KST 144

__global__ __launch_bounds__(256) void attn_mma_kernel()
{
    __shared__ __align__(16) char smem[36864];
    const uint32_t sb = smem_u32(smem);
    const uint32_t sKhi = sb, sKlo = sb + 9216;
    const uint32_t sVf = sb + 18432;

    const int tid = threadIdx.x, lane = tid & 31, warp = tid >> 5;
    const int qi = gridDim.x - 1 - blockIdx.x;
    const int bh = blockIdx.y;
    const size_t bhOff = (size_t)bh * TT * DD;
    const int qBase = qi * 128;

    // ---- stage Q (bf16 copy): rows 128 x 128B, stride 144 ----
    {
        const int row = tid >> 1, half = tid & 1;
        const uint4* ph = (const uint4*)(g_qh + bhOff + (size_t)(qBase + row) * 64 + half * 32);
        const uint4* pl = (const uint4*)(g_ql + bhOff + (size_t)(qBase + row) * 64 + half * 32);
        const uint32_t dh = sb + (uint32_t)row * KST + half * 64;
#pragma unroll
        for (int g = 0; g < 4; g++) {
            uint4 h = ph[g], l = pl[g];
            STS4(dh + g * 16, h.x, h.y, h.z, h.w);
            STS4(dh + 18432 + g * 16, l.x, l.y, l.z, l.w);
        }
    }
    __syncthreads();

    uint32_t qh[4][4], ql[4][4];
    {
        const uint32_t aoff = sb +
            (uint32_t)(warp * 16 + (lane & 7) + ((lane >> 3) & 1) * 8) * KST +
            ((lane >> 4) & 1) * 16;
#pragma unroll
        for (int kh = 0; kh < 4; kh++) {
            ldm4(qh[kh], aoff + kh * 32);
            ldm4(ql[kh], aoff + 18432 + kh * 32);
        }
    }
    __syncthreads();

    float o[8][4];
#pragma unroll
    for (int dn = 0; dn < 8; dn++)
#pragma unroll
        for (int r = 0; r < 4; r++) o[dn][r] = 0.0f;
    float mrow[2] = {-1e30f, -1e30f};
    float lrow[2] = {0.0f, 0.0f};

    const uint32_t boff =
        (uint32_t)((lane & 7) + ((lane >> 4) & 1) * 8) * KST +
        ((lane >> 3) & 1) * 16;
    const uint32_t voff =
        (uint32_t)((lane & 7) + ((lane >> 3) & 1) * 8) * KST +
        ((lane >> 4) & 1) * 16;
    const int jtEnd = 2 * qi + 1;

    for (int jt = 0; jt <= jtEnd; jt++) {
        // ---- copy K (bf16 hi/lo) + V (fp16) tiles ----
        {
            const size_t src0 = bhOff + (size_t)jt * 64 * 64;
#pragma unroll
            for (int g = 0; g < 2; g++) {
                const int id = tid + g * 256;
                const int row = id >> 3, part = id & 7;
                const size_t s = src0 + (size_t)row * 64 + part * 8;
                const uint32_t d = (uint32_t)row * KST + part * 16;
                uint4 v;
                v = *(const uint4*)(g_kh + s); STS4(sKhi + d, v.x, v.y, v.z, v.w);
                v = *(const uint4*)(g_kl + s); STS4(sKlo + d, v.x, v.y, v.z, v.w);
                v = *(const uint4*)(g_vf + s); STS4(sVf + d, v.x, v.y, v.z, v.w);
            }
        }
        __syncthreads();

        // ---- S = Q K^T (split-bf16, 3 MMAs) ----
        float s[8][4];
#pragma unroll
        for (int nt = 0; nt < 8; nt++)
#pragma unroll
            for (int r = 0; r < 4; r++) s[nt][r] = 0.0f;
#pragma unroll
        for (int kh = 0; kh < 4; kh++) {
#pragma unroll
            for (int p = 0; p < 4; p++) {
                uint32_t kbh[4], kbl[4];
                ldm4(kbh, sKhi + boff + p * (16 * KST) + kh * 32);
                ldm4(kbl, sKlo + boff + p * (16 * KST) + kh * 32);
#pragma unroll
                for (int sub = 0; sub < 2; sub++) {
                    float* d = s[2 * p + sub];
                    mma16816(d, qh[kh], &kbh[sub * 2]);
                    mma16816(d, qh[kh], &kbl[sub * 2]);
                    mma16816(d, ql[kh], &kbh[sub * 2]);
                }
            }
        }

        if (jt >= 2 * qi) {
            const int row0 = qBase + warp * 16 + (lane >> 2);
            const int colb = jt * 64 + 2 * (lane & 3);
#pragma unroll
            for (int nt = 0; nt < 8; nt++) {
                const int c = colb + nt * 8;
#pragma unroll
                for (int r = 0; r < 4; r++) {
                    const int row = row0 + ((r >> 1) << 3);
                    const int col = c + (r & 1);
                    if (col > row) s[nt][r] = -1e30f;
                }
            }
        }

        float mx0 = -1e30f, mx1 = -1e30f;
#pragma unroll
        for (int nt = 0; nt < 8; nt++) {
            mx0 = fmaxf(mx0, fmaxf(s[nt][0], s[nt][1]));
            mx1 = fmaxf(mx1, fmaxf(s[nt][2], s[nt][3]));
        }
        mx0 = fmaxf(mx0, __shfl_xor_sync(0xffffffffu, mx0, 1));
        mx0 = fmaxf(mx0, __shfl_xor_sync(0xffffffffu, mx0, 2));
        mx1 = fmaxf(mx1, __shfl_xor_sync(0xffffffffu, mx1, 1));
        mx1 = fmaxf(mx1, __shfl_xor_sync(0xffffffffu, mx1, 2));
        const float mn0 = fmaxf(mrow[0], mx0);
        const float mn1 = fmaxf(mrow[1], mx1);
        const float a0 = exp2f_fast((mrow[0] - mn0) * L2E);
        const float a1 = exp2f_fast((mrow[1] - mn1) * L2E);
        mrow[0] = mn0; mrow[1] = mn1;
        float rs0 = 0.0f, rs1 = 0.0f;
#pragma unroll
        for (int nt = 0; nt < 8; nt++) {
            s[nt][0] = exp2f_fast((s[nt][0] - mn0) * L2E);
            s[nt][1] = exp2f_fast((s[nt][1] - mn0) * L2E);
            s[nt][2] = exp2f_fast((s[nt][2] - mn1) * L2E);
            s[nt][3] = exp2f_fast((s[nt][3] - mn1) * L2E);
            rs0 += s[nt][0] + s[nt][1];
            rs1 += s[nt][2] + s[nt][3];
        }
        rs0 += __shfl_xor_sync(0xffffffffu, rs0, 1);
        rs0 += __shfl_xor_sync(0xffffffffu, rs0, 2);
        rs1 += __shfl_xor_sync(0xffffffffu, rs1, 1);
        rs1 += __shfl_xor_sync(0xffffffffu, rs1, 2);
        lrow[0] = lrow[0] * a0 + rs0;
        lrow[1] = lrow[1] * a1 + rs1;
#pragma unroll
        for (int dn = 0; dn < 8; dn++) {
            o[dn][0] *= a0; o[dn][1] *= a0;
            o[dn][2] *= a1; o[dn][3] *= a1;
        }

        // ---- O += P(fp16) x V(fp16), single MMA per fragment ----
#pragma unroll
        for (int kh = 0; kh < 4; kh++) {
            uint32_t ph[4];
#pragma unroll
            for (int idx = 0; idx < 4; idx++) {
                const int nt = 2 * kh + (idx >> 1);
                const int rb = (idx & 1) * 2;
                ph[idx] = packh2(s[nt][rb], s[nt][rb + 1]);
            }
#pragma unroll
            for (int p = 0; p < 4; p++) {
                uint32_t vb[4];
                ldm4t(vb, sVf + voff + kh * (16 * KST) + p * 32);
#pragma unroll
                for (int sub = 0; sub < 2; sub++)
                    mma16816h(o[2 * p + sub], ph, &vb[sub * 2]);
            }
        }
        __syncthreads();
    }

    const int b = bh / HH, h = bh % HH;
    const float inv0 = 1.0f / lrow[0];
    const float inv1 = 1.0f / lrow[1];
    const int row0 = qBase + warp * 16 + (lane >> 2);
    const int colb = h * 64 + 2 * (lane & 3);
#pragma unroll
    for (int dn = 0; dn < 8; dn++) {
        const int col = colb + dn * 8;
        uint32_t hi, lo;
        split2(o[dn][0] * inv0, o[dn][1] * inv0, hi, lo);
        *(uint32_t*)(g_oh + (size_t)(b * TT + row0) * CC + col) = hi;
        *(uint32_t*)(g_ol + (size_t)(b * TT + row0) * CC + col) = lo;
        split2(o[dn][2] * inv1, o[dn][3] * inv1, hi, lo);
        *(uint32_t*)(g_oh + (size_t)(b * TT + row0 + 8) * CC + col) = hi;
        *(uint32_t*)(g_ol + (size_t)(b * TT + row0 + 8) * CC + col) = lo;
    }
}

// ---------------------------------------------------------------------------
extern "C" void kernel_launch(void* const* d_in, const int* in_sizes, int n_in,
                              void* d_out, int out_size)
{
    const float* x      = (const float*)d_in[0];
    const float* w_qkv  = (const float*)d_in[1];
    const float* w_proj = (const float*)d_in[2];
    const float* rsin   = (const float*)d_in[3];
    const float* rcos   = (const float*)d_in[4];
    float* out = (float*)d_out;

    __nv_bfloat16 *xh, *xl, *wqh, *wql, *wph, *wpl;
    cudaGetSymbolAddress((void**)&xh,  g_xh);
    cudaGetSymbolAddress((void**)&xl,  g_xl);
    cudaGetSymbolAddress((void**)&wqh, g_wqh);
    cudaGetSymbolAddress((void**)&wql, g_wql);
    cudaGetSymbolAddress((void**)&wph, g_wph);
    cudaGetSymbolAddress((void**)&wpl, g_wpl);

    split_kernel<<<1024, 256>>>(x, xh, xl, (BB * TT * CC) / 4);
    split_kernel<<<512, 256>>>(w_qkv, wqh, wql, (3 * CC * CC) / 4);
    split_kernel<<<256, 256>>>(w_proj, wph, wpl, (CC * CC) / 4);

    // QKV: M=8192 (64 x 128), N=2304 (18 x 128)
    gemm_mma_kernel<0><<<dim3(18, 64), 128>>>(rsin, rcos, nullptr);
    // Attention: 16 q-tiles of 128 x 48 (b,h)
    attn_mma_kernel<<<dim3(16, 48), 256>>>();
    // Proj: M=8192, N=768 (6 x 128)
    gemm_mma_kernel<1><<<dim3(6, 64), 128>>>(rsin, rcos, out);
}

// round 15
// speedup vs baseline: 1.4103x; 1.0839x over previous
#include <cuda_runtime.h>
#include <cuda_bf16.h>
#include <cuda_fp16.h>
#include <cstdint>

// Problem constants
#define BB 4
#define TT 2048
#define CC 768
#define HH 12
#define DD 64
#define NQ (BB * HH * TT * DD)

// Pre-split bf16 hi/lo tensors; V and O and w_proj are single fp16
__device__ __nv_bfloat16 g_qh[NQ], g_ql[NQ];
__device__ __nv_bfloat16 g_kh[NQ], g_kl[NQ];
__device__ __half        g_vf[NQ];
__device__ __half        g_of[BB * TT * CC];
__device__ __nv_bfloat16 g_xh[BB * TT * CC], g_xl[BB * TT * CC];
__device__ __nv_bfloat16 g_wqh[3 * CC * CC], g_wql[3 * CC * CC];
__device__ __half        g_wpf[CC * CC];

static __device__ __forceinline__ uint32_t smem_u32(const void* p) {
    uint32_t a;
    asm("{ .reg .u64 t; cvta.to.shared.u64 t, %1; cvt.u32.u64 %0, t; }"
        : "=r"(a) : "l"(p));
    return a;
}

static __device__ __forceinline__ void ldm4(uint32_t* r, uint32_t addr) {
    asm volatile("ldmatrix.sync.aligned.m8n8.x4.shared.b16 {%0,%1,%2,%3}, [%4];"
                 : "=r"(r[0]), "=r"(r[1]), "=r"(r[2]), "=r"(r[3]) : "r"(addr));
}
static __device__ __forceinline__ void ldm4t(uint32_t* r, uint32_t addr) {
    asm volatile("ldmatrix.sync.aligned.m8n8.x4.trans.shared.b16 {%0,%1,%2,%3}, [%4];"
                 : "=r"(r[0]), "=r"(r[1]), "=r"(r[2]), "=r"(r[3]) : "r"(addr));
}

static __device__ __forceinline__ void mma16816(float* d, const uint32_t* a,
                                                const uint32_t* b) {
    asm volatile(
        "mma.sync.aligned.m16n8k16.row.col.f32.bf16.bf16.f32 "
        "{%0,%1,%2,%3}, {%4,%5,%6,%7}, {%8,%9}, {%0,%1,%2,%3};"
        : "+f"(d[0]), "+f"(d[1]), "+f"(d[2]), "+f"(d[3])
        : "r"(a[0]), "r"(a[1]), "r"(a[2]), "r"(a[3]), "r"(b[0]), "r"(b[1]));
}
static __device__ __forceinline__ void mma16816h(float* d, const uint32_t* a,
                                                 const uint32_t* b) {
    asm volatile(
        "mma.sync.aligned.m16n8k16.row.col.f32.f16.f16.f32 "
        "{%0,%1,%2,%3}, {%4,%5,%6,%7}, {%8,%9}, {%0,%1,%2,%3};"
        : "+f"(d[0]), "+f"(d[1]), "+f"(d[2]), "+f"(d[3])
        : "r"(a[0]), "r"(a[1]), "r"(a[2]), "r"(a[3]), "r"(b[0]), "r"(b[1]));
}

static __device__ __forceinline__ void split2(float f0, float f1,
                                              uint32_t& hi, uint32_t& lo) {
    __nv_bfloat16 h0 = __float2bfloat16(f0);
    __nv_bfloat16 h1 = __float2bfloat16(f1);
    __nv_bfloat16 l0 = __float2bfloat16(f0 - __bfloat162float(h0));
    __nv_bfloat16 l1 = __float2bfloat16(f1 - __bfloat162float(h1));
    __nv_bfloat162 hh = __halves2bfloat162(h0, h1);
    __nv_bfloat162 ll = __halves2bfloat162(l0, l1);
    hi = *reinterpret_cast<uint32_t*>(&hh);
    lo = *reinterpret_cast<uint32_t*>(&ll);
}
static __device__ __forceinline__ uint32_t packh2(float f0, float f1) {
    __half2 h = __floats2half2_rn(f0, f1);
    return *reinterpret_cast<uint32_t*>(&h);
}

// FMA-pipe exp2 (no MUFU). Valid for x <= 0; clamps at -126.
static __device__ __forceinline__ float exp2f_fast(float x) {
    x = fmaxf(x, -126.0f);
    float z = x + 12582912.0f;
    int i = __float_as_int(z) - 0x4B400000;
    float f = x - (z - 12582912.0f);
    float p = 0.00133336f;
    p = fmaf(p, f, 0.00961813f);
    p = fmaf(p, f, 0.05550411f);
    p = fmaf(p, f, 0.24022651f);
    p = fmaf(p, f, 0.69314718f);
    p = fmaf(p, f, 1.0f);
    return p * __int_as_float((i + 127) << 23);
}
#define L2E 1.4426950408889634f

#define STS4(addr, a, b, c, d) \
    asm volatile("st.shared.v4.b32 [%0], {%1,%2,%3,%4};" :: \
                 "r"(addr), "r"(a), "r"(b), "r"(c), "r"(d) : "memory")
#define CP16(dst, src) \
    asm volatile("cp.async.ca.shared.global [%0], [%1], 16;" :: \
                 "r"(dst), "l"(src) : "memory")
#define CP_COMMIT() asm volatile("cp.async.commit_group;" ::: "memory")
#define CP_WAIT1()  asm volatile("cp.async.wait_group 1;" ::: "memory")
#define CP_WAIT0()  asm volatile("cp.async.wait_group 0;" ::: "memory")

// ===========================================================================
// Split kernels: fp32 -> bf16 hi/lo; fp32 -> fp16 single
// ===========================================================================
__global__ void split_kernel(const float* __restrict__ src,
                             __nv_bfloat16* __restrict__ h,
                             __nv_bfloat16* __restrict__ l, int n4)
{
    for (int i = blockIdx.x * blockDim.x + threadIdx.x; i < n4;
         i += gridDim.x * blockDim.x) {
        float4 v = ((const float4*)src)[i];
        uint32_t h01, l01, h23, l23;
        split2(v.x, v.y, h01, l01);
        split2(v.z, v.w, h23, l23);
        ((uint2*)h)[i] = make_uint2(h01, h23);
        ((uint2*)l)[i] = make_uint2(l01, l23);
    }
}
__global__ void split_half_kernel(const float* __restrict__ src,
                                  __half* __restrict__ h, int n4)
{
    for (int i = blockIdx.x * blockDim.x + threadIdx.x; i < n4;
         i += gridDim.x * blockDim.x) {
        float4 v = ((const float4*)src)[i];
        ((uint2*)h)[i] = make_uint2(packh2(v.x, v.y), packh2(v.z, v.w));
    }
}

// ===========================================================================
// QKV GEMM (round-11 v4 config): split-bf16 HMMA, cp.async 2-stage,
// warp tile 64x64, CTA 128x128, 4 warps, 2 CTAs/SM.
// RoPE epilogue -> g_qh/ql, g_kh/kl; V -> g_vf (fp16 single).
// ===========================================================================
#define GST 48
#define STAGE_B 24576
#define NCHUNK 48

__global__ __launch_bounds__(128, 2) void gemm_qkv_kernel(
    const float* __restrict__ rsin, const float* __restrict__ rcos)
{
    __shared__ __align__(16) char smem[2 * STAGE_B];
    const uint32_t sb = smem_u32(smem);

    const int tid = threadIdx.x;
    const int lane = tid & 31, warp = tid >> 5;
    const int warpM = warp & 1, warpN = warp >> 1;
    const int mBase = blockIdx.y * 128, nBase = blockIdx.x * 128;

    const __nv_bfloat16* sAh = g_xh + (size_t)(mBase + tid) * 768;
    const __nv_bfloat16* sAl = g_xl + (size_t)(mBase + tid) * 768;
    const __nv_bfloat16* sBh = g_wqh + (size_t)(nBase + tid) * 768;
    const __nv_bfloat16* sBl = g_wql + (size_t)(nBase + tid) * 768;
    const uint32_t dAh = sb + (uint32_t)tid * GST;
    const uint32_t dAl = dAh + 6144;
    const uint32_t dBh = dAh + 12288;
    const uint32_t dBl = dAh + 18432;

    const uint32_t aoff = sb +
        (uint32_t)(warpM * 64 + (lane & 7) + ((lane >> 3) & 1) * 8) * GST +
        ((lane >> 4) & 1) * 16;
    const uint32_t boff = sb + 12288 +
        (uint32_t)(warpN * 64 + (lane & 7) + ((lane >> 4) & 1) * 8) * GST +
        ((lane >> 3) & 1) * 16;

    float acc[4][8][4];
#pragma unroll
    for (int mt = 0; mt < 4; mt++)
#pragma unroll
        for (int nt = 0; nt < 8; nt++)
#pragma unroll
            for (int r = 0; r < 4; r++) acc[mt][nt][r] = 0.0f;

    CP16(dAh, sAh); CP16(dAh + 16, sAh + 8);
    CP16(dAl, sAl); CP16(dAl + 16, sAl + 8);
    CP16(dBh, sBh); CP16(dBh + 16, sBh + 8);
    CP16(dBl, sBl); CP16(dBl + 16, sBl + 8);
    CP_COMMIT();

    for (int c = 0; c < NCHUNK; c++) {
        const uint32_t stOff = (uint32_t)(c & 1) * STAGE_B;
        if (c + 1 < NCHUNK) {
            const uint32_t ns = (uint32_t)((c + 1) & 1) * STAGE_B;
            const int ko = (c + 1) * 16;
            CP16(dAh + ns, sAh + ko); CP16(dAh + ns + 16, sAh + ko + 8);
            CP16(dAl + ns, sAl + ko); CP16(dAl + ns + 16, sAl + ko + 8);
            CP16(dBh + ns, sBh + ko); CP16(dBh + ns + 16, sBh + ko + 8);
            CP16(dBl + ns, sBl + ko); CP16(dBl + ns + 16, sBl + ko + 8);
            CP_COMMIT();
            CP_WAIT1();
        } else {
            CP_WAIT0();
        }
        __syncthreads();

        uint32_t bh[4][4], bl[4][4];
#pragma unroll
        for (int p = 0; p < 4; p++) {
            ldm4(bh[p], boff + stOff + p * (16 * GST));
            ldm4(bl[p], boff + stOff + 6144 + p * (16 * GST));
        }
#pragma unroll
        for (int mt = 0; mt < 4; mt++) {
            uint32_t ah[4], al[4];
            ldm4(ah, aoff + stOff + mt * (16 * GST));
            ldm4(al, aoff + stOff + 6144 + mt * (16 * GST));
#pragma unroll
            for (int nt = 0; nt < 8; nt++) {
                const uint32_t* bhf = &bh[nt >> 1][(nt & 1) * 2];
                const uint32_t* blf = &bl[nt >> 1][(nt & 1) * 2];
                mma16816(acc[mt][nt], ah, bhf);
                mma16816(acc[mt][nt], ah, blf);
                mma16816(acc[mt][nt], al, bhf);
            }
        }
        __syncthreads();
    }

    const int gRow = lane >> 2;
    const int gCol = (lane & 3) * 2;
#pragma unroll
    for (int mt = 0; mt < 4; mt++) {
#pragma unroll
        for (int half = 0; half < 2; half++) {
            const int row_g = mBase + warpM * 64 + mt * 16 + gRow + half * 8;
#pragma unroll
            for (int nt = 0; nt < 8; nt++) {
                const float v1 = acc[mt][nt][half * 2];
                const float v2 = acc[mt][nt][half * 2 + 1];
                const int col_g = nBase + warpN * 64 + nt * 8 + gCol;
                const int b = row_g >> 11, t = row_g & 2047;
                const int s_idx = nBase / 768;
                const int rem = col_g - s_idx * 768;
                const int h = rem >> 6, d = rem & 63;
                const size_t off = ((size_t)(b * HH + h) * TT + t) * DD + d;
                if (s_idx < 2) {
                    const float sc = (s_idx == 0) ? 0.125f : 1.0f;
                    const float sn = rsin[t * 32 + (d >> 1)];
                    const float cs = rcos[t * 32 + (d >> 1)];
                    uint32_t hi, lo;
                    split2((v1 * cs - v2 * sn) * sc,
                           (v1 * sn + v2 * cs) * sc, hi, lo);
                    __nv_bfloat16* dh = (s_idx == 0) ? g_qh : g_kh;
                    __nv_bfloat16* dl = (s_idx == 0) ? g_ql : g_kl;
                    *(uint32_t*)(dh + off) = hi;
                    *(uint32_t*)(dl + off) = lo;
                } else {
                    *(uint32_t*)(g_vf + off) = packh2(v1, v2);
                }
            }
        }
    }
}

// ===========================================================================
// Proj GEMM: fp16 single-MMA (A = g_of, B = g_wpf). Same v4 skeleton.
// Stage: Af[128][48] @0 | Bf[128][48] @6144 = 12288B; 2 stages = 24576B.
// Warp tile 64x64: 8 ldm -> 32 MMAs per chunk.
// ===========================================================================
#define PSTAGE 12288

__global__ __launch_bounds__(128, 2) void gemm_proj_kernel(
    float* __restrict__ outp)
{
    __shared__ __align__(16) char smem[2 * PSTAGE];
    const uint32_t sb = smem_u32(smem);

    const int tid = threadIdx.x;
    const int lane = tid & 31, warp = tid >> 5;
    const int warpM = warp & 1, warpN = warp >> 1;
    const int mBase = blockIdx.y * 128, nBase = blockIdx.x * 128;

    const __half* sA = g_of + (size_t)(mBase + tid) * 768;
    const __half* sB = g_wpf + (size_t)(nBase + tid) * 768;
    const uint32_t dA = sb + (uint32_t)tid * GST;
    const uint32_t dB = dA + 6144;

    const uint32_t aoff = sb +
        (uint32_t)(warpM * 64 + (lane & 7) + ((lane >> 3) & 1) * 8) * GST +
        ((lane >> 4) & 1) * 16;
    const uint32_t boff = sb + 6144 +
        (uint32_t)(warpN * 64 + (lane & 7) + ((lane >> 4) & 1) * 8) * GST +
        ((lane >> 3) & 1) * 16;

    float acc[4][8][4];
#pragma unroll
    for (int mt = 0; mt < 4; mt++)
#pragma unroll
        for (int nt = 0; nt < 8; nt++)
#pragma unroll
            for (int r = 0; r < 4; r++) acc[mt][nt][r] = 0.0f;

    CP16(dA, sA); CP16(dA + 16, sA + 8);
    CP16(dB, sB); CP16(dB + 16, sB + 8);
    CP_COMMIT();

    for (int c = 0; c < NCHUNK; c++) {
        const uint32_t stOff = (uint32_t)(c & 1) * PSTAGE;
        if (c + 1 < NCHUNK) {
            const uint32_t ns = (uint32_t)((c + 1) & 1) * PSTAGE;
            const int ko = (c + 1) * 16;
            CP16(dA + ns, sA + ko); CP16(dA + ns + 16, sA + ko + 8);
            CP16(dB + ns, sB + ko); CP16(dB + ns + 16, sB + ko + 8);
            CP_COMMIT();
            CP_WAIT1();
        } else {
            CP_WAIT0();
        }
        __syncthreads();

        uint32_t bf[4][4];
#pragma unroll
        for (int p = 0; p < 4; p++)
            ldm4(bf[p], boff + stOff + p * (16 * GST));
#pragma unroll
        for (int mt = 0; mt < 4; mt++) {
            uint32_t af[4];
            ldm4(af, aoff + stOff + mt * (16 * GST));
#pragma unroll
            for (int nt = 0; nt < 8; nt++)
                mma16816h(acc[mt][nt], af, &bf[nt >> 1][(nt & 1) * 2]);
        }
        __syncthreads();
    }

    const int gRow = lane >> 2;
    const int gCol = (lane & 3) * 2;
#pragma unroll
    for (int mt = 0; mt < 4; mt++) {
#pragma unroll
        for (int half = 0; half < 2; half++) {
            const int row_g = mBase + warpM * 64 + mt * 16 + gRow + half * 8;
#pragma unroll
            for (int nt = 0; nt < 8; nt++) {
                const int col_g = nBase + warpN * 64 + nt * 8 + gCol;
                *(float2*)(outp + (size_t)row_g * 768 + col_g) =
                    make_float2(acc[mt][nt][half * 2], acc[mt][nt][half * 2 + 1]);
            }
        }
    }
}

// ===========================================================================
// Flash attention: S = split-bf16 3-MMA; O = P(fp16) x V(fp16) single MMA.
// Output written as single fp16 to g_of.
// ===========================================================================
#define KST 144

__global__ __launch_bounds__(256) void attn_mma_kernel()
{
    __shared__ __align__(16) char smem[36864];
    const uint32_t sb = smem_u32(smem);
    const uint32_t sKhi = sb, sKlo = sb + 9216;
    const uint32_t sVf = sb + 18432;

    const int tid = threadIdx.x, lane = tid & 31, warp = tid >> 5;
    const int qi = gridDim.x - 1 - blockIdx.x;
    const int bh = blockIdx.y;
    const size_t bhOff = (size_t)bh * TT * DD;
    const int qBase = qi * 128;

    {
        const int row = tid >> 1, half = tid & 1;
        const uint4* ph = (const uint4*)(g_qh + bhOff + (size_t)(qBase + row) * 64 + half * 32);
        const uint4* pl = (const uint4*)(g_ql + bhOff + (size_t)(qBase + row) * 64 + half * 32);
        const uint32_t dh = sb + (uint32_t)row * KST + half * 64;
#pragma unroll
        for (int g = 0; g < 4; g++) {
            uint4 h = ph[g], l = pl[g];
            STS4(dh + g * 16, h.x, h.y, h.z, h.w);
            STS4(dh + 18432 + g * 16, l.x, l.y, l.z, l.w);
        }
    }
    __syncthreads();

    uint32_t qh[4][4], ql[4][4];
    {
        const uint32_t aoff = sb +
            (uint32_t)(warp * 16 + (lane & 7) + ((lane >> 3) & 1) * 8) * KST +
            ((lane >> 4) & 1) * 16;
#pragma unroll
        for (int kh = 0; kh < 4; kh++) {
            ldm4(qh[kh], aoff + kh * 32);
            ldm4(ql[kh], aoff + 18432 + kh * 32);
        }
    }
    __syncthreads();

    float o[8][4];
#pragma unroll
    for (int dn = 0; dn < 8; dn++)
#pragma unroll
        for (int r = 0; r < 4; r++) o[dn][r] = 0.0f;
    float mrow[2] = {-1e30f, -1e30f};
    float lrow[2] = {0.0f, 0.0f};

    const uint32_t boff =
        (uint32_t)((lane & 7) + ((lane >> 4) & 1) * 8) * KST +
        ((lane >> 3) & 1) * 16;
    const uint32_t voff =
        (uint32_t)((lane & 7) + ((lane >> 3) & 1) * 8) * KST +
        ((lane >> 4) & 1) * 16;
    const int jtEnd = 2 * qi + 1;

    for (int jt = 0; jt <= jtEnd; jt++) {
        {
            const size_t src0 = bhOff + (size_t)jt * 64 * 64;
#pragma unroll
            for (int g = 0; g < 2; g++) {
                const int id = tid + g * 256;
                const int row = id >> 3, part = id & 7;
                const size_t s = src0 + (size_t)row * 64 + part * 8;
                const uint32_t d = (uint32_t)row * KST + part * 16;
                uint4 v;
                v = *(const uint4*)(g_kh + s); STS4(sKhi + d, v.x, v.y, v.z, v.w);
                v = *(const uint4*)(g_kl + s); STS4(sKlo + d, v.x, v.y, v.z, v.w);
                v = *(const uint4*)(g_vf + s); STS4(sVf + d, v.x, v.y, v.z, v.w);
            }
        }
        __syncthreads();

        float s[8][4];
#pragma unroll
        for (int nt = 0; nt < 8; nt++)
#pragma unroll
            for (int r = 0; r < 4; r++) s[nt][r] = 0.0f;
#pragma unroll
        for (int kh = 0; kh < 4; kh++) {
#pragma unroll
            for (int p = 0; p < 4; p++) {
                uint32_t kbh[4], kbl[4];
                ldm4(kbh, sKhi + boff + p * (16 * KST) + kh * 32);
                ldm4(kbl, sKlo + boff + p * (16 * KST) + kh * 32);
#pragma unroll
                for (int sub = 0; sub < 2; sub++) {
                    float* d = s[2 * p + sub];
                    mma16816(d, qh[kh], &kbh[sub * 2]);
                    mma16816(d, qh[kh], &kbl[sub * 2]);
                    mma16816(d, ql[kh], &kbh[sub * 2]);
                }
            }
        }

        if (jt >= 2 * qi) {
            const int row0 = qBase + warp * 16 + (lane >> 2);
            const int colb = jt * 64 + 2 * (lane & 3);
#pragma unroll
            for (int nt = 0; nt < 8; nt++) {
                const int c = colb + nt * 8;
#pragma unroll
                for (int r = 0; r < 4; r++) {
                    const int row = row0 + ((r >> 1) << 3);
                    const int col = c + (r & 1);
                    if (col > row) s[nt][r] = -1e30f;
                }
            }
        }

        float mx0 = -1e30f, mx1 = -1e30f;
#pragma unroll
        for (int nt = 0; nt < 8; nt++) {
            mx0 = fmaxf(mx0, fmaxf(s[nt][0], s[nt][1]));
            mx1 = fmaxf(mx1, fmaxf(s[nt][2], s[nt][3]));
        }
        mx0 = fmaxf(mx0, __shfl_xor_sync(0xffffffffu, mx0, 1));
        mx0 = fmaxf(mx0, __shfl_xor_sync(0xffffffffu, mx0, 2));
        mx1 = fmaxf(mx1, __shfl_xor_sync(0xffffffffu, mx1, 1));
        mx1 = fmaxf(mx1, __shfl_xor_sync(0xffffffffu, mx1, 2));
        const float mn0 = fmaxf(mrow[0], mx0);
        const float mn1 = fmaxf(mrow[1], mx1);
        const float a0 = exp2f_fast((mrow[0] - mn0) * L2E);
        const float a1 = exp2f_fast((mrow[1] - mn1) * L2E);
        mrow[0] = mn0; mrow[1] = mn1;
        float rs0 = 0.0f, rs1 = 0.0f;
#pragma unroll
        for (int nt = 0; nt < 8; nt++) {
            s[nt][0] = exp2f_fast((s[nt][0] - mn0) * L2E);
            s[nt][1] = exp2f_fast((s[nt][1] - mn0) * L2E);
            s[nt][2] = exp2f_fast((s[nt][2] - mn1) * L2E);
            s[nt][3] = exp2f_fast((s[nt][3] - mn1) * L2E);
            rs0 += s[nt][0] + s[nt][1];
            rs1 += s[nt][2] + s[nt][3];
        }
        rs0 += __shfl_xor_sync(0xffffffffu, rs0, 1);
        rs0 += __shfl_xor_sync(0xffffffffu, rs0, 2);
        rs1 += __shfl_xor_sync(0xffffffffu, rs1, 1);
        rs1 += __shfl_xor_sync(0xffffffffu, rs1, 2);
        lrow[0] = lrow[0] * a0 + rs0;
        lrow[1] = lrow[1] * a1 + rs1;
#pragma unroll
        for (int dn = 0; dn < 8; dn++) {
            o[dn][0] *= a0; o[dn][1] *= a0;
            o[dn][2] *= a1; o[dn][3] *= a1;
        }

#pragma unroll
        for (int kh = 0; kh < 4; kh++) {
            uint32_t ph[4];
#pragma unroll
            for (int idx = 0; idx < 4; idx++) {
                const int nt = 2 * kh + (idx >> 1);
                const int rb = (idx & 1) * 2;
                ph[idx] = packh2(s[nt][rb], s[nt][rb + 1]);
            }
#pragma unroll
            for (int p = 0; p < 4; p++) {
                uint32_t vb[4];
                ldm4t(vb, sVf + voff + kh * (16 * KST) + p * 32);
#pragma unroll
                for (int sub = 0; sub < 2; sub++)
                    mma16816h(o[2 * p + sub], ph, &vb[sub * 2]);
            }
        }
        __syncthreads();
    }

    const int b = bh / HH, h = bh % HH;
    const float inv0 = 1.0f / lrow[0];
    const float inv1 = 1.0f / lrow[1];
    const int row0 = qBase + warp * 16 + (lane >> 2);
    const int colb = h * 64 + 2 * (lane & 3);
#pragma unroll
    for (int dn = 0; dn < 8; dn++) {
        const int col = colb + dn * 8;
        *(uint32_t*)(g_of + (size_t)(b * TT + row0) * CC + col) =
            packh2(o[dn][0] * inv0, o[dn][1] * inv0);
        *(uint32_t*)(g_of + (size_t)(b * TT + row0 + 8) * CC + col) =
            packh2(o[dn][2] * inv1, o[dn][3] * inv1);
    }
}

// ---------------------------------------------------------------------------
extern "C" void kernel_launch(void* const* d_in, const int* in_sizes, int n_in,
                              void* d_out, int out_size)
{
    const float* x      = (const float*)d_in[0];
    const float* w_qkv  = (const float*)d_in[1];
    const float* w_proj = (const float*)d_in[2];
    const float* rsin   = (const float*)d_in[3];
    const float* rcos   = (const float*)d_in[4];
    float* out = (float*)d_out;

    __nv_bfloat16 *xh, *xl, *wqh, *wql;
    __half *wpf;
    cudaGetSymbolAddress((void**)&xh,  g_xh);
    cudaGetSymbolAddress((void**)&xl,  g_xl);
    cudaGetSymbolAddress((void**)&wqh, g_wqh);
    cudaGetSymbolAddress((void**)&wql, g_wql);
    cudaGetSymbolAddress((void**)&wpf, g_wpf);

    split_kernel<<<1024, 256>>>(x, xh, xl, (BB * TT * CC) / 4);
    split_kernel<<<512, 256>>>(w_qkv, wqh, wql, (3 * CC * CC) / 4);
    split_half_kernel<<<256, 256>>>(w_proj, wpf, (CC * CC) / 4);

    // QKV: M=8192 (64 x 128), N=2304 (18 x 128)
    gemm_qkv_kernel<<<dim3(18, 64), 128>>>(rsin, rcos);
    // Attention: 16 q-tiles of 128 x 48 (b,h)
    attn_mma_kernel<<<dim3(16, 48), 256>>>();
    // Proj: M=8192, N=768 (6 x 128)
    gemm_proj_kernel<<<dim3(6, 64), 128>>>(out);
}

// round 16
// speedup vs baseline: 1.6709x; 1.1847x over previous
#include <cuda_runtime.h>
#include <cuda_bf16.h>
#include <cuda_fp16.h>
#include <cstdint>

// Problem constants
#define BB 4
#define TT 2048
#define CC 768
#define HH 12
#define DD 64
#define NQ (BB * HH * TT * DD)

// q/k stored bf16 hi/lo (S-GEMM precision); V, O, x, weights in fp16 forms
__device__ __nv_bfloat16 g_qh[NQ], g_ql[NQ];
__device__ __nv_bfloat16 g_kh[NQ], g_kl[NQ];
__device__ __half        g_vf[NQ];
__device__ __half        g_of[BB * TT * CC];
__device__ __half        g_xf[BB * TT * CC];
__device__ __half        g_wqh[3 * CC * CC], g_wql[3 * CC * CC];
__device__ __half        g_wpf[CC * CC];

static __device__ __forceinline__ uint32_t smem_u32(const void* p) {
    uint32_t a;
    asm("{ .reg .u64 t; cvta.to.shared.u64 t, %1; cvt.u32.u64 %0, t; }"
        : "=r"(a) : "l"(p));
    return a;
}

static __device__ __forceinline__ void ldm4(uint32_t* r, uint32_t addr) {
    asm volatile("ldmatrix.sync.aligned.m8n8.x4.shared.b16 {%0,%1,%2,%3}, [%4];"
                 : "=r"(r[0]), "=r"(r[1]), "=r"(r[2]), "=r"(r[3]) : "r"(addr));
}
static __device__ __forceinline__ void ldm4t(uint32_t* r, uint32_t addr) {
    asm volatile("ldmatrix.sync.aligned.m8n8.x4.trans.shared.b16 {%0,%1,%2,%3}, [%4];"
                 : "=r"(r[0]), "=r"(r[1]), "=r"(r[2]), "=r"(r[3]) : "r"(addr));
}

static __device__ __forceinline__ void mma16816(float* d, const uint32_t* a,
                                                const uint32_t* b) {
    asm volatile(
        "mma.sync.aligned.m16n8k16.row.col.f32.bf16.bf16.f32 "
        "{%0,%1,%2,%3}, {%4,%5,%6,%7}, {%8,%9}, {%0,%1,%2,%3};"
        : "+f"(d[0]), "+f"(d[1]), "+f"(d[2]), "+f"(d[3])
        : "r"(a[0]), "r"(a[1]), "r"(a[2]), "r"(a[3]), "r"(b[0]), "r"(b[1]));
}
static __device__ __forceinline__ void mma16816h(float* d, const uint32_t* a,
                                                 const uint32_t* b) {
    asm volatile(
        "mma.sync.aligned.m16n8k16.row.col.f32.f16.f16.f32 "
        "{%0,%1,%2,%3}, {%4,%5,%6,%7}, {%8,%9}, {%0,%1,%2,%3};"
        : "+f"(d[0]), "+f"(d[1]), "+f"(d[2]), "+f"(d[3])
        : "r"(a[0]), "r"(a[1]), "r"(a[2]), "r"(a[3]), "r"(b[0]), "r"(b[1]));
}

static __device__ __forceinline__ void split2(float f0, float f1,
                                              uint32_t& hi, uint32_t& lo) {
    __nv_bfloat16 h0 = __float2bfloat16(f0);
    __nv_bfloat16 h1 = __float2bfloat16(f1);
    __nv_bfloat16 l0 = __float2bfloat16(f0 - __bfloat162float(h0));
    __nv_bfloat16 l1 = __float2bfloat16(f1 - __bfloat162float(h1));
    __nv_bfloat162 hh = __halves2bfloat162(h0, h1);
    __nv_bfloat162 ll = __halves2bfloat162(l0, l1);
    hi = *reinterpret_cast<uint32_t*>(&hh);
    lo = *reinterpret_cast<uint32_t*>(&ll);
}
static __device__ __forceinline__ uint32_t packh2(float f0, float f1) {
    __half2 h = __floats2half2_rn(f0, f1);
    return *reinterpret_cast<uint32_t*>(&h);
}
static __device__ __forceinline__ void splith2(float f0, float f1,
                                               uint32_t& hi, uint32_t& lo) {
    __half h0 = __float2half_rn(f0);
    __half h1 = __float2half_rn(f1);
    __half l0 = __float2half_rn(f0 - __half2float(h0));
    __half l1 = __float2half_rn(f1 - __half2float(h1));
    __half2 hh = __halves2half2(h0, h1);
    __half2 ll = __halves2half2(l0, l1);
    hi = *reinterpret_cast<uint32_t*>(&hh);
    lo = *reinterpret_cast<uint32_t*>(&ll);
}

// FMA-pipe exp2 (no MUFU). Valid for x <= 0; clamps at -126.
static __device__ __forceinline__ float exp2f_fast(float x) {
    x = fmaxf(x, -126.0f);
    float z = x + 12582912.0f;
    int i = __float_as_int(z) - 0x4B400000;
    float f = x - (z - 12582912.0f);
    float p = 0.00133336f;
    p = fmaf(p, f, 0.00961813f);
    p = fmaf(p, f, 0.05550411f);
    p = fmaf(p, f, 0.24022651f);
    p = fmaf(p, f, 0.69314718f);
    p = fmaf(p, f, 1.0f);
    return p * __int_as_float((i + 127) << 23);
}
#define L2E 1.4426950408889634f

#define STS4(addr, a, b, c, d) \
    asm volatile("st.shared.v4.b32 [%0], {%1,%2,%3,%4};" :: \
                 "r"(addr), "r"(a), "r"(b), "r"(c), "r"(d) : "memory")
#define CP16(dst, src) \
    asm volatile("cp.async.ca.shared.global [%0], [%1], 16;" :: \
                 "r"(dst), "l"(src) : "memory")
#define CP_COMMIT() asm volatile("cp.async.commit_group;" ::: "memory")
#define CP_WAIT1()  asm volatile("cp.async.wait_group 1;" ::: "memory")
#define CP_WAIT0()  asm volatile("cp.async.wait_group 0;" ::: "memory")

// ===========================================================================
// Split kernels
// ===========================================================================
__global__ void split_half_kernel(const float* __restrict__ src,
                                  __half* __restrict__ h, int n4)
{
    for (int i = blockIdx.x * blockDim.x + threadIdx.x; i < n4;
         i += gridDim.x * blockDim.x) {
        float4 v = ((const float4*)src)[i];
        ((uint2*)h)[i] = make_uint2(packh2(v.x, v.y), packh2(v.z, v.w));
    }
}
__global__ void split_half2_kernel(const float* __restrict__ src,
                                   __half* __restrict__ h,
                                   __half* __restrict__ l, int n4)
{
    for (int i = blockIdx.x * blockDim.x + threadIdx.x; i < n4;
         i += gridDim.x * blockDim.x) {
        float4 v = ((const float4*)src)[i];
        uint32_t h01, l01, h23, l23;
        splith2(v.x, v.y, h01, l01);
        splith2(v.z, v.w, h23, l23);
        ((uint2*)h)[i] = make_uint2(h01, h23);
        ((uint2*)l)[i] = make_uint2(l01, l23);
    }
}

// ===========================================================================
// QKV GEMM (v5): A = x fp16 single; B = w_qkv fp16 hi/lo.
// ISV=0 (q/k, 12 n-blocks): acc = Ah*Bh + Ah*Bl   (2 MMAs)
// ISV=1 (v,   6 n-blocks): acc = Ah*Bh            (1 MMA); Bl unused
// CTA 128x128, 4 warps (2x2), warp tile 64x64, K-chunk 16, cp.async 2-stage.
// Stage: A[128][48] @0 | Bh @6144 | Bl @12288 = 18432B; 2 stages = 36864B.
// Epilogue: ISV=0 RoPE -> g_qh/ql or g_kh/kl (bf16 hi/lo); ISV=1 -> g_vf fp16.
// ===========================================================================
#define GST 48
#define QSTAGE 18432
#define NCHUNK 48

template <int ISV>
__global__ __launch_bounds__(128, 2) void gemm_qkv_kernel(
    const float* __restrict__ rsin, const float* __restrict__ rcos)
{
    __shared__ __align__(16) char smem[2 * QSTAGE];
    const uint32_t sb = smem_u32(smem);

    const int tid = threadIdx.x;
    const int lane = tid & 31, warp = tid >> 5;
    const int warpM = warp & 1, warpN = warp >> 1;
    const int mBase = blockIdx.y * 128;
    const int nBase = blockIdx.x * 128 + (ISV ? 1536 : 0);

    const __half* sA  = g_xf  + (size_t)(mBase + tid) * 768;
    const __half* sBh = g_wqh + (size_t)(nBase + tid) * 768;
    const __half* sBl = g_wql + (size_t)(nBase + tid) * 768;
    const uint32_t dA  = sb + (uint32_t)tid * GST;
    const uint32_t dBh = dA + 6144;
    const uint32_t dBl = dA + 12288;

    const uint32_t aoff = sb +
        (uint32_t)(warpM * 64 + (lane & 7) + ((lane >> 3) & 1) * 8) * GST +
        ((lane >> 4) & 1) * 16;
    const uint32_t boff = sb + 6144 +
        (uint32_t)(warpN * 64 + (lane & 7) + ((lane >> 4) & 1) * 8) * GST +
        ((lane >> 3) & 1) * 16;

    float acc[4][8][4];
#pragma unroll
    for (int mt = 0; mt < 4; mt++)
#pragma unroll
        for (int nt = 0; nt < 8; nt++)
#pragma unroll
            for (int r = 0; r < 4; r++) acc[mt][nt][r] = 0.0f;

    CP16(dA, sA); CP16(dA + 16, sA + 8);
    CP16(dBh, sBh); CP16(dBh + 16, sBh + 8);
    if (!ISV) { CP16(dBl, sBl); CP16(dBl + 16, sBl + 8); }
    CP_COMMIT();

    for (int c = 0; c < NCHUNK; c++) {
        const uint32_t stOff = (uint32_t)(c & 1) * QSTAGE;
        if (c + 1 < NCHUNK) {
            const uint32_t ns = (uint32_t)((c + 1) & 1) * QSTAGE;
            const int ko = (c + 1) * 16;
            CP16(dA + ns, sA + ko); CP16(dA + ns + 16, sA + ko + 8);
            CP16(dBh + ns, sBh + ko); CP16(dBh + ns + 16, sBh + ko + 8);
            if (!ISV) { CP16(dBl + ns, sBl + ko); CP16(dBl + ns + 16, sBl + ko + 8); }
            CP_COMMIT();
            CP_WAIT1();
        } else {
            CP_WAIT0();
        }
        __syncthreads();

        uint32_t bh[4][4], bl[4][4];
#pragma unroll
        for (int p = 0; p < 4; p++) {
            ldm4(bh[p], boff + stOff + p * (16 * GST));
            if (!ISV) ldm4(bl[p], boff + stOff + 6144 + p * (16 * GST));
        }
#pragma unroll
        for (int mt = 0; mt < 4; mt++) {
            uint32_t ah[4];
            ldm4(ah, aoff + stOff + mt * (16 * GST));
#pragma unroll
            for (int nt = 0; nt < 8; nt++) {
                mma16816h(acc[mt][nt], ah, &bh[nt >> 1][(nt & 1) * 2]);
                if (!ISV)
                    mma16816h(acc[mt][nt], ah, &bl[nt >> 1][(nt & 1) * 2]);
            }
        }
        __syncthreads();
    }

    const int gRow = lane >> 2;
    const int gCol = (lane & 3) * 2;
#pragma unroll
    for (int mt = 0; mt < 4; mt++) {
#pragma unroll
        for (int half = 0; half < 2; half++) {
            const int row_g = mBase + warpM * 64 + mt * 16 + gRow + half * 8;
#pragma unroll
            for (int nt = 0; nt < 8; nt++) {
                const float v1 = acc[mt][nt][half * 2];
                const float v2 = acc[mt][nt][half * 2 + 1];
                const int col_g = nBase + warpN * 64 + nt * 8 + gCol;
                const int b = row_g >> 11, t = row_g & 2047;
                const int s_idx = nBase / 768;
                const int rem = col_g - s_idx * 768;
                const int h = rem >> 6, d = rem & 63;
                const size_t off = ((size_t)(b * HH + h) * TT + t) * DD + d;
                if (!ISV) {
                    const float sc = (s_idx == 0) ? 0.125f : 1.0f;
                    const float sn = rsin[t * 32 + (d >> 1)];
                    const float cs = rcos[t * 32 + (d >> 1)];
                    uint32_t hi, lo;
                    split2((v1 * cs - v2 * sn) * sc,
                           (v1 * sn + v2 * cs) * sc, hi, lo);
                    __nv_bfloat16* dh = (s_idx == 0) ? g_qh : g_kh;
                    __nv_bfloat16* dl = (s_idx == 0) ? g_ql : g_kl;
                    *(uint32_t*)(dh + off) = hi;
                    *(uint32_t*)(dl + off) = lo;
                } else {
                    *(uint32_t*)(g_vf + off) = packh2(v1, v2);
                }
            }
        }
    }
}

// ===========================================================================
// Proj GEMM: fp16 single-MMA (A = g_of, B = g_wpf), round-15 config.
// ===========================================================================
#define PSTAGE 12288

__global__ __launch_bounds__(128, 2) void gemm_proj_kernel(
    float* __restrict__ outp)
{
    __shared__ __align__(16) char smem[2 * PSTAGE];
    const uint32_t sb = smem_u32(smem);

    const int tid = threadIdx.x;
    const int lane = tid & 31, warp = tid >> 5;
    const int warpM = warp & 1, warpN = warp >> 1;
    const int mBase = blockIdx.y * 128, nBase = blockIdx.x * 128;

    const __half* sA = g_of + (size_t)(mBase + tid) * 768;
    const __half* sB = g_wpf + (size_t)(nBase + tid) * 768;
    const uint32_t dA = sb + (uint32_t)tid * GST;
    const uint32_t dB = dA + 6144;

    const uint32_t aoff = sb +
        (uint32_t)(warpM * 64 + (lane & 7) + ((lane >> 3) & 1) * 8) * GST +
        ((lane >> 4) & 1) * 16;
    const uint32_t boff = sb + 6144 +
        (uint32_t)(warpN * 64 + (lane & 7) + ((lane >> 4) & 1) * 8) * GST +
        ((lane >> 3) & 1) * 16;

    float acc[4][8][4];
#pragma unroll
    for (int mt = 0; mt < 4; mt++)
#pragma unroll
        for (int nt = 0; nt < 8; nt++)
#pragma unroll
            for (int r = 0; r < 4; r++) acc[mt][nt][r] = 0.0f;

    CP16(dA, sA); CP16(dA + 16, sA + 8);
    CP16(dB, sB); CP16(dB + 16, sB + 8);
    CP_COMMIT();

    for (int c = 0; c < NCHUNK; c++) {
        const uint32_t stOff = (uint32_t)(c & 1) * PSTAGE;
        if (c + 1 < NCHUNK) {
            const uint32_t ns = (uint32_t)((c + 1) & 1) * PSTAGE;
            const int ko = (c + 1) * 16;
            CP16(dA + ns, sA + ko); CP16(dA + ns + 16, sA + ko + 8);
            CP16(dB + ns, sB + ko); CP16(dB + ns + 16, sB + ko + 8);
            CP_COMMIT();
            CP_WAIT1();
        } else {
            CP_WAIT0();
        }
        __syncthreads();

        uint32_t bf[4][4];
#pragma unroll
        for (int p = 0; p < 4; p++)
            ldm4(bf[p], boff + stOff + p * (16 * GST));
#pragma unroll
        for (int mt = 0; mt < 4; mt++) {
            uint32_t af[4];
            ldm4(af, aoff + stOff + mt * (16 * GST));
#pragma unroll
            for (int nt = 0; nt < 8; nt++)
                mma16816h(acc[mt][nt], af, &bf[nt >> 1][(nt & 1) * 2]);
        }
        __syncthreads();
    }

    const int gRow = lane >> 2;
    const int gCol = (lane & 3) * 2;
#pragma unroll
    for (int mt = 0; mt < 4; mt++) {
#pragma unroll
        for (int half = 0; half < 2; half++) {
            const int row_g = mBase + warpM * 64 + mt * 16 + gRow + half * 8;
#pragma unroll
            for (int nt = 0; nt < 8; nt++) {
                const int col_g = nBase + warpN * 64 + nt * 8 + gCol;
                *(float2*)(outp + (size_t)row_g * 768 + col_g) =
                    make_float2(acc[mt][nt][half * 2], acc[mt][nt][half * 2 + 1]);
            }
        }
    }
}

// ===========================================================================
// Flash attention (unchanged from round 15): S = split-bf16 3-MMA;
// O = P(fp16) x V(fp16) single MMA; output fp16 to g_of.
// ===========================================================================
#define KST 144

__global__ __launch_bounds__(256) void attn_mma_kernel()
{
    __shared__ __align__(16) char smem[36864];
    const uint32_t sb = smem_u32(smem);
    const uint32_t sKhi = sb, sKlo = sb + 9216;
    const uint32_t sVf = sb + 18432;

    const int tid = threadIdx.x, lane = tid & 31, warp = tid >> 5;
    const int qi = gridDim.x - 1 - blockIdx.x;
    const int bh = blockIdx.y;
    const size_t bhOff = (size_t)bh * TT * DD;
    const int qBase = qi * 128;

    {
        const int row = tid >> 1, half = tid & 1;
        const uint4* ph = (const uint4*)(g_qh + bhOff + (size_t)(qBase + row) * 64 + half * 32);
        const uint4* pl = (const uint4*)(g_ql + bhOff + (size_t)(qBase + row) * 64 + half * 32);
        const uint32_t dh = sb + (uint32_t)row * KST + half * 64;
#pragma unroll
        for (int g = 0; g < 4; g++) {
            uint4 h = ph[g], l = pl[g];
            STS4(dh + g * 16, h.x, h.y, h.z, h.w);
            STS4(dh + 18432 + g * 16, l.x, l.y, l.z, l.w);
        }
    }
    __syncthreads();

    uint32_t qh[4][4], ql[4][4];
    {
        const uint32_t aoff = sb +
            (uint32_t)(warp * 16 + (lane & 7) + ((lane >> 3) & 1) * 8) * KST +
            ((lane >> 4) & 1) * 16;
#pragma unroll
        for (int kh = 0; kh < 4; kh++) {
            ldm4(qh[kh], aoff + kh * 32);
            ldm4(ql[kh], aoff + 18432 + kh * 32);
        }
    }
    __syncthreads();

    float o[8][4];
#pragma unroll
    for (int dn = 0; dn < 8; dn++)
#pragma unroll
        for (int r = 0; r < 4; r++) o[dn][r] = 0.0f;
    float mrow[2] = {-1e30f, -1e30f};
    float lrow[2] = {0.0f, 0.0f};

    const uint32_t boff =
        (uint32_t)((lane & 7) + ((lane >> 4) & 1) * 8) * KST +
        ((lane >> 3) & 1) * 16;
    const uint32_t voff =
        (uint32_t)((lane & 7) + ((lane >> 3) & 1) * 8) * KST +
        ((lane >> 4) & 1) * 16;
    const int jtEnd = 2 * qi + 1;

    for (int jt = 0; jt <= jtEnd; jt++) {
        {
            const size_t src0 = bhOff + (size_t)jt * 64 * 64;
#pragma unroll
            for (int g = 0; g < 2; g++) {
                const int id = tid + g * 256;
                const int row = id >> 3, part = id & 7;
                const size_t s = src0 + (size_t)row * 64 + part * 8;
                const uint32_t d = (uint32_t)row * KST + part * 16;
                uint4 v;
                v = *(const uint4*)(g_kh + s); STS4(sKhi + d, v.x, v.y, v.z, v.w);
                v = *(const uint4*)(g_kl + s); STS4(sKlo + d, v.x, v.y, v.z, v.w);
                v = *(const uint4*)(g_vf + s); STS4(sVf + d, v.x, v.y, v.z, v.w);
            }
        }
        __syncthreads();

        float s[8][4];
#pragma unroll
        for (int nt = 0; nt < 8; nt++)
#pragma unroll
            for (int r = 0; r < 4; r++) s[nt][r] = 0.0f;
#pragma unroll
        for (int kh = 0; kh < 4; kh++) {
#pragma unroll
            for (int p = 0; p < 4; p++) {
                uint32_t kbh[4], kbl[4];
                ldm4(kbh, sKhi + boff + p * (16 * KST) + kh * 32);
                ldm4(kbl, sKlo + boff + p * (16 * KST) + kh * 32);
#pragma unroll
                for (int sub = 0; sub < 2; sub++) {
                    float* d = s[2 * p + sub];
                    mma16816(d, qh[kh], &kbh[sub * 2]);
                    mma16816(d, qh[kh], &kbl[sub * 2]);
                    mma16816(d, ql[kh], &kbh[sub * 2]);
                }
            }
        }

        if (jt >= 2 * qi) {
            const int row0 = qBase + warp * 16 + (lane >> 2);
            const int colb = jt * 64 + 2 * (lane & 3);
#pragma unroll
            for (int nt = 0; nt < 8; nt++) {
                const int c = colb + nt * 8;
#pragma unroll
                for (int r = 0; r < 4; r++) {
                    const int row = row0 + ((r >> 1) << 3);
                    const int col = c + (r & 1);
                    if (col > row) s[nt][r] = -1e30f;
                }
            }
        }

        float mx0 = -1e30f, mx1 = -1e30f;
#pragma unroll
        for (int nt = 0; nt < 8; nt++) {
            mx0 = fmaxf(mx0, fmaxf(s[nt][0], s[nt][1]));
            mx1 = fmaxf(mx1, fmaxf(s[nt][2], s[nt][3]));
        }
        mx0 = fmaxf(mx0, __shfl_xor_sync(0xffffffffu, mx0, 1));
        mx0 = fmaxf(mx0, __shfl_xor_sync(0xffffffffu, mx0, 2));
        mx1 = fmaxf(mx1, __shfl_xor_sync(0xffffffffu, mx1, 1));
        mx1 = fmaxf(mx1, __shfl_xor_sync(0xffffffffu, mx1, 2));
        const float mn0 = fmaxf(mrow[0], mx0);
        const float mn1 = fmaxf(mrow[1], mx1);
        const float a0 = exp2f_fast((mrow[0] - mn0) * L2E);
        const float a1 = exp2f_fast((mrow[1] - mn1) * L2E);
        mrow[0] = mn0; mrow[1] = mn1;
        float rs0 = 0.0f, rs1 = 0.0f;
#pragma unroll
        for (int nt = 0; nt < 8; nt++) {
            s[nt][0] = exp2f_fast((s[nt][0] - mn0) * L2E);
            s[nt][1] = exp2f_fast((s[nt][1] - mn0) * L2E);
            s[nt][2] = exp2f_fast((s[nt][2] - mn1) * L2E);
            s[nt][3] = exp2f_fast((s[nt][3] - mn1) * L2E);
            rs0 += s[nt][0] + s[nt][1];
            rs1 += s[nt][2] + s[nt][3];
        }
        rs0 += __shfl_xor_sync(0xffffffffu, rs0, 1);
        rs0 += __shfl_xor_sync(0xffffffffu, rs0, 2);
        rs1 += __shfl_xor_sync(0xffffffffu, rs1, 1);
        rs1 += __shfl_xor_sync(0xffffffffu, rs1, 2);
        lrow[0] = lrow[0] * a0 + rs0;
        lrow[1] = lrow[1] * a1 + rs1;
#pragma unroll
        for (int dn = 0; dn < 8; dn++) {
            o[dn][0] *= a0; o[dn][1] *= a0;
            o[dn][2] *= a1; o[dn][3] *= a1;
        }

#pragma unroll
        for (int kh = 0; kh < 4; kh++) {
            uint32_t ph[4];
#pragma unroll
            for (int idx = 0; idx < 4; idx++) {
                const int nt = 2 * kh + (idx >> 1);
                const int rb = (idx & 1) * 2;
                ph[idx] = packh2(s[nt][rb], s[nt][rb + 1]);
            }
#pragma unroll
            for (int p = 0; p < 4; p++) {
                uint32_t vb[4];
                ldm4t(vb, sVf + voff + kh * (16 * KST) + p * 32);
#pragma unroll
                for (int sub = 0; sub < 2; sub++)
                    mma16816h(o[2 * p + sub], ph, &vb[sub * 2]);
            }
        }
        __syncthreads();
    }

    const int b = bh / HH, h = bh % HH;
    const float inv0 = 1.0f / lrow[0];
    const float inv1 = 1.0f / lrow[1];
    const int row0 = qBase + warp * 16 + (lane >> 2);
    const int colb = h * 64 + 2 * (lane & 3);
#pragma unroll
    for (int dn = 0; dn < 8; dn++) {
        const int col = colb + dn * 8;
        *(uint32_t*)(g_of + (size_t)(b * TT + row0) * CC + col) =
            packh2(o[dn][0] * inv0, o[dn][1] * inv0);
        *(uint32_t*)(g_of + (size_t)(b * TT + row0 + 8) * CC + col) =
            packh2(o[dn][2] * inv1, o[dn][3] * inv1);
    }
}

// ---------------------------------------------------------------------------
extern "C" void kernel_launch(void* const* d_in, const int* in_sizes, int n_in,
                              void* d_out, int out_size)
{
    const float* x      = (const float*)d_in[0];
    const float* w_qkv  = (const float*)d_in[1];
    const float* w_proj = (const float*)d_in[2];
    const float* rsin   = (const float*)d_in[3];
    const float* rcos   = (const float*)d_in[4];
    float* out = (float*)d_out;

    __half *xf, *wqh, *wql, *wpf;
    cudaGetSymbolAddress((void**)&xf,  g_xf);
    cudaGetSymbolAddress((void**)&wqh, g_wqh);
    cudaGetSymbolAddress((void**)&wql, g_wql);
    cudaGetSymbolAddress((void**)&wpf, g_wpf);

    split_half_kernel<<<1024, 256>>>(x, xf, (BB * TT * CC) / 4);
    split_half2_kernel<<<512, 256>>>(w_qkv, wqh, wql, (3 * CC * CC) / 4);
    split_half_kernel<<<256, 256>>>(w_proj, wpf, (CC * CC) / 4);

    // QKV q/k: N-blocks 0-11 (2-MMA); v: blocks 0-5 of s_idx 2 (1-MMA)
    gemm_qkv_kernel<0><<<dim3(12, 64), 128>>>(rsin, rcos);
    gemm_qkv_kernel<1><<<dim3(6, 64), 128>>>(rsin, rcos);
    // Attention: 16 q-tiles of 128 x 48 (b,h)
    attn_mma_kernel<<<dim3(16, 48), 256>>>();
    // Proj: M=8192, N=768 (6 x 128)
    gemm_proj_kernel<<<dim3(6, 64), 128>>>(out);
}